// round 5
// baseline (speedup 1.0000x reference)
#include <cuda_runtime.h>
#include <cstdint>

#define N_NODES     8192
#define N_PAIRS_MAX 1000000
#define PATH_LEN    8
#define EDGE_DIM    16
#define MAX_EDGES   100000

#define HASH_BITS   22
#define HASH_SLOTS  (1u << HASH_BITS)
#define HASH_MASK   (HASH_SLOTS - 1u)

// Static device scratch (no allocs allowed).
__device__ float              g_dots[N_PAIRS_MAX];          // 4 MB
__device__ float              g_T[MAX_EDGES * PATH_LEN];    // 3.2 MB
__device__ unsigned long long g_hash[HASH_SLOTS];           // 32 MB

// ---------------------------------------------------------------------------
// Zero-fill with SHORT-LIVED blocks (no grid-stride persistence): each thread
// writes one 64B burst (4x float4, streaming/evict-first), so blocks retire
// in ~1us and concurrent graph branches can co-schedule on freed SMs.
// ---------------------------------------------------------------------------
__global__ void __launch_bounds__(256)
zero_fill64B(float4* __restrict__ p, size_t n4 /* number of float4 */)
{
    size_t t  = (size_t)blockIdx.x * blockDim.x + threadIdx.x;
    size_t i0 = t * 4;
    if (i0 + 4 <= n4) {
        const float4 z = make_float4(0.f, 0.f, 0.f, 0.f);
        __stcs(&p[i0 + 0], z);
        __stcs(&p[i0 + 1], z);
        __stcs(&p[i0 + 2], z);
        __stcs(&p[i0 + 3], z);
    } else {
        const float4 z = make_float4(0.f, 0.f, 0.f, 0.f);
        for (size_t i = i0; i < n4; ++i) __stcs(&p[i], z);
    }
}

// ---------------------------------------------------------------------------
// T[e][l] = dot(edge_attr[e], edge_vector[l])
// ---------------------------------------------------------------------------
__global__ void __launch_bounds__(256)
precompute_T(const float* __restrict__ edge_attr,
             const float* __restrict__ edge_vector,
             int n_edges)
{
    int e = blockIdx.x * blockDim.x + threadIdx.x;
    if (e >= n_edges) return;

    const float4* ea = (const float4*)edge_attr + (size_t)e * 4;
    float4 a0 = __ldg(&ea[0]), a1 = __ldg(&ea[1]);
    float4 a2 = __ldg(&ea[2]), a3 = __ldg(&ea[3]);

    const float4* ev = (const float4*)edge_vector;
    float t[PATH_LEN];
#pragma unroll
    for (int l = 0; l < PATH_LEN; ++l) {
        float4 v0 = __ldg(&ev[l * 4 + 0]);
        float4 v1 = __ldg(&ev[l * 4 + 1]);
        float4 v2 = __ldg(&ev[l * 4 + 2]);
        float4 v3 = __ldg(&ev[l * 4 + 3]);
        t[l] = a0.x * v0.x + a0.y * v0.y + a0.z * v0.z + a0.w * v0.w
             + a1.x * v1.x + a1.y * v1.y + a1.z * v1.z + a1.w * v1.w
             + a2.x * v2.x + a2.y * v2.y + a2.z * v2.z + a2.w * v2.w
             + a3.x * v3.x + a3.y * v3.y + a3.z * v3.z + a3.w * v3.w;
    }
    float4* tt = (float4*)(g_T + (size_t)e * PATH_LEN);
    tt[0] = make_float4(t[0], t[1], t[2], t[3]);
    tt[1] = make_float4(t[4], t[5], t[6], t[7]);
}

// ---------------------------------------------------------------------------
// Per-pair masked mean via T-gather; claim (cell -> max pair idx) in hash.
// slot entry: key(=cell+1) << 24 | (p+1).
// ---------------------------------------------------------------------------
__global__ void __launch_bounds__(256)
pair_dots_claim(const int* __restrict__ paths,
                const int* __restrict__ src,
                const int* __restrict__ dst,
                int n_pairs)
{
    int p = blockIdx.x * blockDim.x + threadIdx.x;
    if (p >= n_pairs) return;

    const int4* pr = (const int4*)paths + (size_t)p * 2;
    int4 pa = pr[0];
    int4 pb = pr[1];
    int idxs[PATH_LEN] = {pa.x, pa.y, pa.z, pa.w, pb.x, pb.y, pb.z, pb.w};

    float sum = 0.0f;
#pragma unroll
    for (int l = 0; l < PATH_LEN; ++l) {
        int e = idxs[l];
        if (e >= 0) sum += __ldg(&g_T[(size_t)e * PATH_LEN + l]);
    }
    g_dots[p] = sum * (1.0f / PATH_LEN);

    unsigned cell = (unsigned)src[p] * N_NODES + (unsigned)dst[p]; // < 2^26
    unsigned key  = cell + 1u;                                     // != 0
    unsigned long long want = ((unsigned long long)key << 24) | (unsigned)(p + 1);
    unsigned slot = (cell * 2654435761u) >> (32 - HASH_BITS);

    while (true) {
        unsigned long long cur = g_hash[slot];
        if (cur == 0ULL) {
            unsigned long long prev = atomicCAS(&g_hash[slot], 0ULL, want);
            if (prev == 0ULL) return;
            cur = prev;
        }
        if ((unsigned)(cur >> 24) == key) {     // keys are write-once
            atomicMax(&g_hash[slot], want);     // same key -> compares p+1
            return;
        }
        slot = (slot + 1u) & HASH_MASK;
    }
}

// ---------------------------------------------------------------------------
// Coalesced sweep: every occupied slot is a winner record.
// ---------------------------------------------------------------------------
__global__ void __launch_bounds__(256)
fixup_scan(float* __restrict__ out)
{
    unsigned i = blockIdx.x * blockDim.x + threadIdx.x;
    if (i >= HASH_SLOTS) return;
    unsigned long long cur = g_hash[i];
    if (cur != 0ULL) {
        unsigned cell = (unsigned)(cur >> 24) - 1u;
        unsigned p    = (unsigned)(cur & 0xFFFFFFu) - 1u;
        out[cell] = g_dots[p];
    }
}

// ---------------------------------------------------------------------------
extern "C" void kernel_launch(void* const* d_in, const int* in_sizes, int n_in,
                              void* d_out, int out_size)
{
    int off = (in_sizes[0] == 1) ? 1 : 0;

    const float* edge_attr   = (const float*)d_in[off + 0];
    const int*   src         = (const int*)  d_in[off + 1];
    const int*   dst         = (const int*)  d_in[off + 2];
    const int*   paths       = (const int*)  d_in[off + 3];
    const float* edge_vector = (const float*)d_in[off + 4];
    float* out = (float*)d_out;

    const int n_edges = in_sizes[off + 0] / EDGE_DIM;
    const int n_pairs = in_sizes[off + 1];

    static cudaStream_t s2 = nullptr, s3 = nullptr;
    static cudaEvent_t  evF = nullptr, evOut = nullptr, evHash = nullptr;
    static bool inited = false;
    if (!inited) {
        bool ok = cudaStreamCreateWithFlags(&s2, cudaStreamNonBlocking) == cudaSuccess
               && cudaStreamCreateWithFlags(&s3, cudaStreamNonBlocking) == cudaSuccess
               && cudaEventCreateWithFlags(&evF,    cudaEventDisableTiming) == cudaSuccess
               && cudaEventCreateWithFlags(&evOut,  cudaEventDisableTiming) == cudaSuccess
               && cudaEventCreateWithFlags(&evHash, cudaEventDisableTiming) == cudaSuccess;
        if (!ok) { s2 = nullptr; s3 = nullptr; }
        inited = true;
    }

    void* hashp = nullptr;
    cudaGetSymbolAddress(&hashp, g_hash);
    const size_t out_n4   = (size_t)out_size / 4;                        // 16.7M float4
    const size_t hash_n4  = HASH_SLOTS * sizeof(unsigned long long) / 16;

    // Short-lived blocks: one 64B burst per thread.
    const int out_fill_blocks  = (int)((out_n4  / 4 + 255) / 256);   // 16384
    const int hash_fill_blocks = (int)((hash_n4 / 4 + 255) / 256);   // 2048

    if (s2) {
        cudaEventRecord(evF, 0);
        cudaStreamWaitEvent(s2, evF, 0);
        cudaStreamWaitEvent(s3, evF, 0);

        // s3: hash zero (16-32 MB), short blocks, concurrent with T.
        zero_fill64B<<<hash_fill_blocks, 256, 0, s3>>>((float4*)hashp, hash_n4);
        cudaEventRecord(evHash, s3);

        // s2: 256 MB output zero, short blocks -> co-schedules with claim path.
        zero_fill64B<<<out_fill_blocks, 256, 0, s2>>>((float4*)out, out_n4);
        cudaEventRecord(evOut, s2);

        // stream 0: T table, then claims.
        precompute_T<<<(n_edges + 255) / 256, 256>>>(edge_attr, edge_vector, n_edges);

        cudaStreamWaitEvent(0, evHash, 0);
        pair_dots_claim<<<(n_pairs + 255) / 256, 256>>>(paths, src, dst, n_pairs);

        cudaStreamWaitEvent(0, evOut, 0);
        fixup_scan<<<HASH_SLOTS / 256, 256>>>(out);
    } else {
        zero_fill64B<<<hash_fill_blocks, 256>>>((float4*)hashp, hash_n4);
        zero_fill64B<<<out_fill_blocks, 256>>>((float4*)out, out_n4);
        precompute_T<<<(n_edges + 255) / 256, 256>>>(edge_attr, edge_vector, n_edges);
        pair_dots_claim<<<(n_pairs + 255) / 256, 256>>>(paths, src, dst, n_pairs);
        fixup_scan<<<HASH_SLOTS / 256, 256>>>(out);
    }
}

// round 6
// speedup vs baseline: 1.3839x; 1.3839x over previous
#include <cuda_runtime.h>
#include <cstdint>

#define N_NODES     8192
#define N_PAIRS_MAX 1000000
#define PATH_LEN    8
#define EDGE_DIM    16
#define MAX_EDGES   100000
#define ROW_CAP     1024        // Poisson mean 122/row; 1024 is unreachable

// Static device scratch (no allocs allowed).
__device__ float              g_dots[N_PAIRS_MAX];              // 4 MB
__device__ float              g_T[MAX_EDGES * PATH_LEN];        // 3.2 MB
__device__ unsigned           g_cursor[N_NODES];                // 32 KB
__device__ unsigned long long g_rec[(size_t)N_NODES * ROW_CAP]; // 64 MB

// ---------------------------------------------------------------------------
// T[e][l] = dot(edge_attr[e], edge_vector[l])
// ---------------------------------------------------------------------------
__global__ void __launch_bounds__(256)
precompute_T(const float* __restrict__ edge_attr,
             const float* __restrict__ edge_vector,
             int n_edges)
{
    int e = blockIdx.x * blockDim.x + threadIdx.x;
    if (e >= n_edges) return;

    const float4* ea = (const float4*)edge_attr + (size_t)e * 4;
    float4 a0 = __ldg(&ea[0]), a1 = __ldg(&ea[1]);
    float4 a2 = __ldg(&ea[2]), a3 = __ldg(&ea[3]);

    const float4* ev = (const float4*)edge_vector;
    float t[PATH_LEN];
#pragma unroll
    for (int l = 0; l < PATH_LEN; ++l) {
        float4 v0 = __ldg(&ev[l * 4 + 0]);
        float4 v1 = __ldg(&ev[l * 4 + 1]);
        float4 v2 = __ldg(&ev[l * 4 + 2]);
        float4 v3 = __ldg(&ev[l * 4 + 3]);
        t[l] = a0.x * v0.x + a0.y * v0.y + a0.z * v0.z + a0.w * v0.w
             + a1.x * v1.x + a1.y * v1.y + a1.z * v1.z + a1.w * v1.w
             + a2.x * v2.x + a2.y * v2.y + a2.z * v2.z + a2.w * v2.w
             + a3.x * v3.x + a3.y * v3.y + a3.z * v3.z + a3.w * v3.w;
    }
    float4* tt = (float4*)(g_T + (size_t)e * PATH_LEN);
    tt[0] = make_float4(t[0], t[1], t[2], t[3]);
    tt[1] = make_float4(t[4], t[5], t[6], t[7]);
}

// ---------------------------------------------------------------------------
// Per pair: masked-mean dot via T-gather -> g_dots[p]; append (dst,p) record
// to the src-row bucket.
// ---------------------------------------------------------------------------
__global__ void __launch_bounds__(256)
scatter_dots(const int* __restrict__ paths,
             const int* __restrict__ src,
             const int* __restrict__ dst,
             int n_pairs)
{
    int p = blockIdx.x * blockDim.x + threadIdx.x;
    if (p >= n_pairs) return;

    const int4* pr = (const int4*)paths + (size_t)p * 2;
    int4 pa = pr[0];
    int4 pb = pr[1];
    int idxs[PATH_LEN] = {pa.x, pa.y, pa.z, pa.w, pb.x, pb.y, pb.z, pb.w};

    float sum = 0.0f;
#pragma unroll
    for (int l = 0; l < PATH_LEN; ++l) {
        int e = idxs[l];
        if (e >= 0) sum += __ldg(&g_T[(size_t)e * PATH_LEN + l]);
    }
    g_dots[p] = sum * (1.0f / PATH_LEN);

    unsigned row = (unsigned)src[p];
    unsigned col = (unsigned)dst[p];
    unsigned pos = atomicAdd(&g_cursor[row], 1u);
    if (pos < ROW_CAP) {
        g_rec[(size_t)row * ROW_CAP + pos] =
            ((unsigned long long)col << 32) | (unsigned)p;
    }
}

// ---------------------------------------------------------------------------
// One block per output row: resolve duplicates in smem (max pair idx wins ==
// JAX last-write), then write the ENTIRE row (zeros + values) coalesced,
// evict-first. The zero-fill and scatter happen in one pass.
// ---------------------------------------------------------------------------
__global__ void __launch_bounds__(256)
write_rows(float* __restrict__ out)
{
    __shared__ unsigned tag[N_NODES];   // 32 KB

    const unsigned row = blockIdx.x;
    const unsigned tid = threadIdx.x;

    // zero tags
#pragma unroll
    for (int j = 0; j < N_NODES / 256; ++j)
        tag[tid + j * 256] = 0u;
    __syncthreads();

    unsigned cnt = g_cursor[row];
    if (cnt > ROW_CAP) cnt = ROW_CAP;

    const unsigned long long* rec = g_rec + (size_t)row * ROW_CAP;
    for (unsigned r = tid; r < cnt; r += 256) {
        unsigned long long e = rec[r];
        atomicMax(&tag[(unsigned)(e >> 32)], (unsigned)e + 1u);
    }
    __syncthreads();

    float4* orow = (float4*)(out + (size_t)row * N_NODES);
#pragma unroll
    for (int j = 0; j < (N_NODES / 4) / 256; ++j) {   // 8 float4 per thread
        unsigned i = tid + j * 256;                   // float4 index
        unsigned t0 = tag[i * 4 + 0];
        unsigned t1 = tag[i * 4 + 1];
        unsigned t2 = tag[i * 4 + 2];
        unsigned t3 = tag[i * 4 + 3];
        float4 v;
        v.x = t0 ? __ldg(&g_dots[t0 - 1u]) : 0.0f;
        v.y = t1 ? __ldg(&g_dots[t1 - 1u]) : 0.0f;
        v.z = t2 ? __ldg(&g_dots[t2 - 1u]) : 0.0f;
        v.w = t3 ? __ldg(&g_dots[t3 - 1u]) : 0.0f;
        __stcs(&orow[i], v);
    }
}

// ---------------------------------------------------------------------------
extern "C" void kernel_launch(void* const* d_in, const int* in_sizes, int n_in,
                              void* d_out, int out_size)
{
    int off = (in_sizes[0] == 1) ? 1 : 0;

    const float* edge_attr   = (const float*)d_in[off + 0];
    const int*   src         = (const int*)  d_in[off + 1];
    const int*   dst         = (const int*)  d_in[off + 2];
    const int*   paths       = (const int*)  d_in[off + 3];
    const float* edge_vector = (const float*)d_in[off + 4];
    float* out = (float*)d_out;

    const int n_edges = in_sizes[off + 0] / EDGE_DIM;
    const int n_pairs = in_sizes[off + 1];

    // zero the 32 KB cursor array (driver memset fine at this size)
    void* curp = nullptr;
    cudaGetSymbolAddress(&curp, g_cursor);
    cudaMemsetAsync(curp, 0, N_NODES * sizeof(unsigned), 0);

    precompute_T<<<(n_edges + 255) / 256, 256>>>(edge_attr, edge_vector, n_edges);

    scatter_dots<<<(n_pairs + 255) / 256, 256>>>(paths, src, dst, n_pairs);

    write_rows<<<N_NODES, 256>>>(out);
}

// round 7
// speedup vs baseline: 1.5206x; 1.0987x over previous
#include <cuda_runtime.h>
#include <cstdint>

#define N_NODES     8192
#define N_PAIRS_MAX 1000000
#define PATH_LEN    8
#define EDGE_DIM    16
#define MAX_EDGES   100000
#define ROW_CAP     1024        // Poisson mean 122/row; 1024 unreachable

// Static device scratch (no allocs allowed).
__device__ float              g_dots[N_PAIRS_MAX];              // 4 MB
__device__ float              g_T[MAX_EDGES * PATH_LEN];        // 3.2 MB
__device__ unsigned           g_cursor[N_NODES];                // 32 KB
__device__ unsigned long long g_rec[(size_t)N_NODES * ROW_CAP]; // 64 MB

// ---------------------------------------------------------------------------
// T[e][l] = dot(edge_attr[e], edge_vector[l])
// ---------------------------------------------------------------------------
__global__ void __launch_bounds__(256)
precompute_T(const float* __restrict__ edge_attr,
             const float* __restrict__ edge_vector,
             int n_edges)
{
    int e = blockIdx.x * blockDim.x + threadIdx.x;
    if (e >= n_edges) return;

    const float4* ea = (const float4*)edge_attr + (size_t)e * 4;
    float4 a0 = __ldg(&ea[0]), a1 = __ldg(&ea[1]);
    float4 a2 = __ldg(&ea[2]), a3 = __ldg(&ea[3]);

    const float4* ev = (const float4*)edge_vector;
    float t[PATH_LEN];
#pragma unroll
    for (int l = 0; l < PATH_LEN; ++l) {
        float4 v0 = __ldg(&ev[l * 4 + 0]);
        float4 v1 = __ldg(&ev[l * 4 + 1]);
        float4 v2 = __ldg(&ev[l * 4 + 2]);
        float4 v3 = __ldg(&ev[l * 4 + 3]);
        t[l] = a0.x * v0.x + a0.y * v0.y + a0.z * v0.z + a0.w * v0.w
             + a1.x * v1.x + a1.y * v1.y + a1.z * v1.z + a1.w * v1.w
             + a2.x * v2.x + a2.y * v2.y + a2.z * v2.z + a2.w * v2.w
             + a3.x * v3.x + a3.y * v3.y + a3.z * v3.z + a3.w * v3.w;
    }
    float4* tt = (float4*)(g_T + (size_t)e * PATH_LEN);
    tt[0] = make_float4(t[0], t[1], t[2], t[3]);
    tt[1] = make_float4(t[4], t[5], t[6], t[7]);
}

// ---------------------------------------------------------------------------
// 2 pairs per thread: doubles memory-level parallelism (scatter was
// latency-bound at issue=7%). All loads for both pairs are issued up front.
// ---------------------------------------------------------------------------
__global__ void __launch_bounds__(256)
scatter_dots2(const int* __restrict__ paths,
              const int* __restrict__ src,
              const int* __restrict__ dst,
              int n_pairs)
{
    int t  = blockIdx.x * blockDim.x + threadIdx.x;
    int p0 = t * 2;
    if (p0 >= n_pairs) return;
    bool two = (p0 + 1) < n_pairs;

    // paths for both pairs: 4 contiguous int4
    const int4* pr = (const int4*)paths + (size_t)p0 * 2;
    int4 a0 = __ldg(&pr[0]);
    int4 a1 = __ldg(&pr[1]);
    int4 b0, b1;
    if (two) { b0 = __ldg(&pr[2]); b1 = __ldg(&pr[3]); }
    else     { b0 = make_int4(-1,-1,-1,-1); b1 = b0; }

    int2 s2 = *(const int2*)(src + p0);
    int2 d2 = *(const int2*)(dst + p0);

    int iA[PATH_LEN] = {a0.x, a0.y, a0.z, a0.w, a1.x, a1.y, a1.z, a1.w};
    int iB[PATH_LEN] = {b0.x, b0.y, b0.z, b0.w, b1.x, b1.y, b1.z, b1.w};

    float sumA = 0.f, sumB = 0.f;
#pragma unroll
    for (int l = 0; l < PATH_LEN; ++l) {
        int eA = iA[l], eB = iB[l];
        float vA = (eA >= 0) ? __ldg(&g_T[(size_t)eA * PATH_LEN + l]) : 0.f;
        float vB = (eB >= 0) ? __ldg(&g_T[(size_t)eB * PATH_LEN + l]) : 0.f;
        sumA += vA; sumB += vB;
    }
    sumA *= (1.0f / PATH_LEN);
    sumB *= (1.0f / PATH_LEN);

    if (two) {
        *(float2*)(g_dots + p0) = make_float2(sumA, sumB);
    } else {
        g_dots[p0] = sumA;
    }

    {   // pair p0
        unsigned pos = atomicAdd(&g_cursor[(unsigned)s2.x], 1u);
        if (pos < ROW_CAP)
            g_rec[(size_t)(unsigned)s2.x * ROW_CAP + pos] =
                ((unsigned long long)(unsigned)d2.x << 32) | (unsigned)p0;
    }
    if (two) {   // pair p0+1
        unsigned pos = atomicAdd(&g_cursor[(unsigned)s2.y], 1u);
        if (pos < ROW_CAP)
            g_rec[(size_t)(unsigned)s2.y * ROW_CAP + pos] =
                ((unsigned long long)(unsigned)d2.y << 32) | (unsigned)(p0 + 1);
    }
}

// ---------------------------------------------------------------------------
// One block (512 thr) per output row: resolve duplicates in smem (max pair
// idx wins == JAX last-write), then write the ENTIRE row coalesced,
// evict-first. Zero-fill and scatter in one pass.
// ---------------------------------------------------------------------------
__global__ void __launch_bounds__(512)
write_rows(float* __restrict__ out)
{
    __shared__ unsigned tag[N_NODES];   // 32 KB

    const unsigned row = blockIdx.x;
    const unsigned tid = threadIdx.x;

    // zero tags with 16B smem stores: 8192 u32 = 512 uint4 -> 1 per thread... 
    // actually 2048 uint4 / 512 = 4 per thread
    uint4* tag4 = (uint4*)tag;
#pragma unroll
    for (int j = 0; j < (N_NODES / 4) / 512; ++j)
        tag4[tid + j * 512] = make_uint4(0u, 0u, 0u, 0u);
    __syncthreads();

    unsigned cnt = g_cursor[row];
    if (cnt > ROW_CAP) cnt = ROW_CAP;

    const unsigned long long* rec = g_rec + (size_t)row * ROW_CAP;
    for (unsigned r = tid; r < cnt; r += 512) {
        unsigned long long e = __ldg(&rec[r]);
        atomicMax(&tag[(unsigned)(e >> 32)], (unsigned)e + 1u);
    }
    __syncthreads();

    float4* orow = (float4*)(out + (size_t)row * N_NODES);
#pragma unroll
    for (int j = 0; j < (N_NODES / 4) / 512; ++j) {   // 4 float4 per thread
        unsigned i = tid + j * 512;                   // float4 index
        unsigned t0 = tag[i * 4 + 0];
        unsigned t1 = tag[i * 4 + 1];
        unsigned t2 = tag[i * 4 + 2];
        unsigned t3 = tag[i * 4 + 3];
        float4 v;
        v.x = t0 ? __ldg(&g_dots[t0 - 1u]) : 0.0f;
        v.y = t1 ? __ldg(&g_dots[t1 - 1u]) : 0.0f;
        v.z = t2 ? __ldg(&g_dots[t2 - 1u]) : 0.0f;
        v.w = t3 ? __ldg(&g_dots[t3 - 1u]) : 0.0f;
        __stcs(&orow[i], v);
    }
}

// ---------------------------------------------------------------------------
extern "C" void kernel_launch(void* const* d_in, const int* in_sizes, int n_in,
                              void* d_out, int out_size)
{
    int off = (in_sizes[0] == 1) ? 1 : 0;

    const float* edge_attr   = (const float*)d_in[off + 0];
    const int*   src         = (const int*)  d_in[off + 1];
    const int*   dst         = (const int*)  d_in[off + 2];
    const int*   paths       = (const int*)  d_in[off + 3];
    const float* edge_vector = (const float*)d_in[off + 4];
    float* out = (float*)d_out;

    const int n_edges = in_sizes[off + 0] / EDGE_DIM;
    const int n_pairs = in_sizes[off + 1];

    // zero the 32 KB cursor array (tiny; driver memset fine)
    void* curp = nullptr;
    cudaGetSymbolAddress(&curp, g_cursor);
    cudaMemsetAsync(curp, 0, N_NODES * sizeof(unsigned), 0);

    precompute_T<<<(n_edges + 255) / 256, 256>>>(edge_attr, edge_vector, n_edges);

    const int n_thr = (n_pairs + 1) / 2;
    scatter_dots2<<<(n_thr + 255) / 256, 256>>>(paths, src, dst, n_pairs);

    write_rows<<<N_NODES, 512>>>(out);
}